// round 4
// baseline (speedup 1.0000x reference)
#include <cuda_runtime.h>
#include <cstddef>

// Problem constants (fixed by setup_inputs)
constexpr int B = 8;
constexpr int C = 144;
constexpr int N = 4096;
constexpr int K = 16;
constexpr int G = 9;
constexpr int D = 16;          // C / G
constexpr int NTILE = 64;      // points per block
constexpr int NBLK_N = N / NTILE;

constexpr int FEAT_ELEMS = B * C * N;      // 4718592
constexpr int CENT_ELEMS = B * G * N;      // 294912
constexpr int IDX_ELEMS  = B * N * K;      // 524288
constexpr int NBLOCKS    = B * G * NBLK_N; // 4608 (= CENT_ELEMS / 64)

// Scratch: point-major transposed copies of queryandkey and value.
__device__ __align__(16) float g_qk_t[(size_t)B * G * N * D];
__device__ __align__(16) float g_v_t [(size_t)B * G * N * D];

// Index-dtype flag: 1 if idx_knn is int64, 0 if int32.
__device__ int g_idx_is64;

// ---------------------------------------------------------------------------
// Detect idx dtype. For little-endian int64 values in [0, N), every odd
// 32-bit word is zero. For int32 indices, odd words are real index values
// (P[1024 random indices in [0,4096) all zero] ~ 0). Max read offset:
// word 2047 = 8KB, within a 2MB int32 buffer.
// ---------------------------------------------------------------------------
__global__ void detect_idx_kernel(const unsigned int* __restrict__ idx_raw)
{
    __shared__ unsigned int any;
    if (threadIdx.x == 0) any = 0u;
    __syncthreads();
    unsigned int v = idx_raw[2 * threadIdx.x + 1] |
                     idx_raw[2 * (threadIdx.x + 256) + 1] |
                     idx_raw[2 * (threadIdx.x + 512) + 1] |
                     idx_raw[2 * (threadIdx.x + 768) + 1];
    if (v) atomicOr(&any, 1u);
    __syncthreads();
    if (threadIdx.x == 0) g_idx_is64 = (any == 0u) ? 1 : 0;
}

// ---------------------------------------------------------------------------
// Transpose (B, C, N) -> (B, G, N, D) for both tensors, and zero the
// centrality output region (64 elements per block, stream-ordered before
// the attn kernel's atomics).
// ---------------------------------------------------------------------------
__global__ void __launch_bounds__(256) transpose_kernel(
    const float* __restrict__ qk, const float* __restrict__ val,
    float* __restrict__ cent)
{
    __shared__ float tile[D][NTILE + 1];

    const int blk   = blockIdx.x;
    const int ntile = blk % NBLK_N;
    const int bg    = blk / NBLK_N;
    const int g     = bg % G;
    const int b     = bg / G;
    const int n0    = ntile * NTILE;
    const int tid   = threadIdx.x;

    // zero this block's 64-element slice of centrality
    if (cent != nullptr && tid < 64)
        cent[(size_t)blk * 64 + tid] = 0.0f;

    const size_t src_off = ((size_t)b * C + (size_t)g * D) * N + n0;
    const size_t dst_off = ((size_t)bg * N + n0) * D;

    {
        const float* src = qk + src_off;
        float* dst = g_qk_t + dst_off;
        #pragma unroll
        for (int r = 0; r < 4; r++) {
            int e = tid + r * 256;
            int j = e >> 6, nn = e & 63;
            tile[j][nn] = src[(size_t)j * N + nn];
        }
        __syncthreads();
        #pragma unroll
        for (int r = 0; r < 4; r++) {
            int e = tid + r * 256;
            int nn = e >> 4, j = e & 15;
            dst[nn * D + j] = tile[j][nn];
        }
        __syncthreads();
    }
    {
        const float* src = val + src_off;
        float* dst = g_v_t + dst_off;
        #pragma unroll
        for (int r = 0; r < 4; r++) {
            int e = tid + r * 256;
            int j = e >> 6, nn = e & 63;
            tile[j][nn] = src[(size_t)j * N + nn];
        }
        __syncthreads();
        #pragma unroll
        for (int r = 0; r < 4; r++) {
            int e = tid + r * 256;
            int nn = e >> 4, j = e & 15;
            dst[nn * D + j] = tile[j][nn];
        }
    }
}

// ---------------------------------------------------------------------------
// Main fused kernel: attention + softmax + feature + centrality scatter.
// 4 lanes per point (float4 over the 16 channels), 64 points per 256-thr block.
// ---------------------------------------------------------------------------
__global__ void __launch_bounds__(256) attn_kernel(
    const void* __restrict__ idx_raw,
    float* __restrict__ out,           // feature region
    float* __restrict__ cent)          // centrality region (may be null)
{
    const float4* __restrict__ qkt = reinterpret_cast<const float4*>(g_qk_t);
    const float4* __restrict__ vt  = reinterpret_cast<const float4*>(g_v_t);

    const int blk   = blockIdx.x;
    const int ntile = blk % NBLK_N;
    const int bg    = blk / NBLK_N;
    const int g     = bg % G;
    const int b     = bg / G;
    const int n0    = ntile * NTILE;

    const int tid  = threadIdx.x;
    const int p    = tid >> 2;          // point within tile (0..63)
    const int L    = tid & 3;           // lane within point (4 channels each)
    const int n    = n0 + p;
    const int lane = tid & 31;
    const int base_lane = lane & ~3;
    const unsigned FULL = 0xffffffffu;

    const size_t bgN = (size_t)bg * N;

    // --- load this lane's 4 neighbor indices (dtype-dispatched), clamp ---
    const size_t ibase = ((size_t)b * N + n) * K + 4 * L;
    int my_idx[4];
    if (g_idx_is64) {
        const long long* ip = reinterpret_cast<const long long*>(idx_raw) + ibase;
        longlong2 e0 = *reinterpret_cast<const longlong2*>(ip);
        longlong2 e1 = *reinterpret_cast<const longlong2*>(ip + 2);
        my_idx[0] = (int)e0.x; my_idx[1] = (int)e0.y;
        my_idx[2] = (int)e1.x; my_idx[3] = (int)e1.y;
    } else {
        const int4* ip = reinterpret_cast<const int4*>(
            reinterpret_cast<const int*>(idx_raw) + ibase);
        int4 e = *ip;
        my_idx[0] = e.x; my_idx[1] = e.y; my_idx[2] = e.z; my_idx[3] = e.w;
    }
    #pragma unroll
    for (int i = 0; i < 4; i++)
        my_idx[i] = min(max(my_idx[i], 0), N - 1);   // structural OOB guard

    // broadcast all 16 indices to each lane of the 4-lane group
    int ms[16];
    #pragma unroll
    for (int k = 0; k < 16; k++)
        ms[k] = __shfl_sync(FULL, my_idx[k & 3], base_lane + (k >> 2));

    // --- query vector (this lane's 4 channels) ---
    const float4 q = qkt[(bgN + n) * 4 + L];

    // --- attention logits: dot(q, key[m_k]) reduced over 4 lanes ---
    float att[16];
    #pragma unroll
    for (int k = 0; k < 16; k++) {
        float4 kk = qkt[(bgN + (size_t)ms[k]) * 4 + L];
        float s = fmaf(q.x, kk.x, fmaf(q.y, kk.y, fmaf(q.z, kk.z, q.w * kk.w)));
        s += __shfl_xor_sync(FULL, s, 1);
        s += __shfl_xor_sync(FULL, s, 2);
        att[k] = s;                     // all 4 lanes hold identical value
    }

    // --- softmax over K=16 (redundant per lane, registers only) ---
    float mx = att[0];
    #pragma unroll
    for (int k = 1; k < 16; k++) mx = fmaxf(mx, att[k]);
    float sum = 0.0f;
    #pragma unroll
    for (int k = 0; k < 16; k++) { att[k] = __expf(att[k] - mx); sum += att[k]; }
    const float inv = 1.0f / sum;
    #pragma unroll
    for (int k = 0; k < 16; k++) att[k] *= inv;

    // --- feature: sum_k att[k] * value[m_k] (this lane's 4 channels) ---
    float4 acc = make_float4(0.f, 0.f, 0.f, 0.f);
    #pragma unroll
    for (int k = 0; k < 16; k++) {
        float4 vv = vt[(bgN + (size_t)ms[k]) * 4 + L];
        acc.x = fmaf(att[k], vv.x, acc.x);
        acc.y = fmaf(att[k], vv.y, acc.y);
        acc.z = fmaf(att[k], vv.z, acc.z);
        acc.w = fmaf(att[k], vv.w, acc.w);
    }

    // --- centrality scatter: each lane handles its own 4 neighbors ---
    if (cent != nullptr) {
        #pragma unroll
        for (int i = 0; i < 4; i++)
            atomicAdd(&cent[bgN + (size_t)my_idx[i]], att[4 * L + i]);
    }

    // --- stage feature in smem, write coalesced in (B, C, N) layout ---
    __shared__ float ftile[NTILE][D + 1];
    ftile[p][4 * L + 0] = acc.x;
    ftile[p][4 * L + 1] = acc.y;
    ftile[p][4 * L + 2] = acc.z;
    ftile[p][4 * L + 3] = acc.w;
    __syncthreads();

    float* fout = out + ((size_t)b * C + (size_t)g * D) * N + n0;
    #pragma unroll
    for (int r = 0; r < 4; r++) {
        int e = tid + r * 256;
        int j = e >> 6, nn = e & 63;
        fout[(size_t)j * N + nn] = ftile[nn][j];
    }
}

// ---------------------------------------------------------------------------
// Launch
// ---------------------------------------------------------------------------
extern "C" void kernel_launch(void* const* d_in, const int* in_sizes, int n_in,
                              void* d_out, int out_size)
{
    // Resolve inputs by element count (robust to ordering):
    //   queryandkey / value: the two inputs with B*C*N elements (qk first)
    //   idx_knn: the input with B*N*K elements
    const float* qk  = nullptr;
    const float* val = nullptr;
    const void*  idx = nullptr;

    for (int i = 0; i < n_in; i++) {
        if (in_sizes[i] == FEAT_ELEMS) {
            if (qk == nullptr)       qk  = (const float*)d_in[i];
            else if (val == nullptr) val = (const float*)d_in[i];
        } else if (in_sizes[i] == IDX_ELEMS) {
            idx = d_in[i];
        }
    }
    if (qk == nullptr || val == nullptr || idx == nullptr) {
        qk  = (const float*)d_in[4];
        val = (const float*)d_in[5];
        idx = d_in[6];
    }

    float* out  = (float*)d_out;                   // feature (B*C*N) first
    float* cent = nullptr;                         // then centrality (B*G*N)
    if (out_size >= FEAT_ELEMS + CENT_ELEMS)
        cent = out + (size_t)FEAT_ELEMS;

    detect_idx_kernel<<<1, 256>>>((const unsigned int*)idx);
    transpose_kernel<<<NBLOCKS, 256>>>(qk, val, cent);
    attn_kernel<<<NBLOCKS, 256>>>(idx, out, cent);
}

// round 6
// speedup vs baseline: 1.0217x; 1.0217x over previous
#include <cuda_runtime.h>
#include <cstddef>

// Problem constants (fixed by setup_inputs)
constexpr int B = 8;
constexpr int C = 144;
constexpr int N = 4096;
constexpr int K = 16;
constexpr int G = 9;
constexpr int D = 16;          // C / G
constexpr int NTILE = 64;      // points per block
constexpr int NBLK_N = N / NTILE;

constexpr int FEAT_ELEMS = B * C * N;      // 4718592
constexpr int CENT_ELEMS = B * G * N;      // 294912
constexpr int IDX_ELEMS  = B * N * K;      // 524288
constexpr int NBLOCKS    = B * G * NBLK_N; // 4608 (= CENT_ELEMS / 64)

// Scratch: point-major transposed copies of queryandkey and value.
__device__ __align__(16) float g_qk_t[(size_t)B * G * N * D];
__device__ __align__(16) float g_v_t [(size_t)B * G * N * D];

// Index-dtype flag: 1 if idx_knn is int64, 0 if int32.
__device__ int g_idx_is64;

// ---------------------------------------------------------------------------
// Transpose (B, C, N) -> (B, G, N, D) for both tensors, zero the centrality
// region, and (block 0 only) detect the idx dtype.
//
// Dtype detection: for little-endian int64 values in [0, N), every odd 32-bit
// word is zero; for int32 indices the odd words are real index values
// (P[1024 random indices in [0,4096) all zero] ~ 0). Max read offset is word
// 2047 = 8KB, within a 2MB int32 allocation.
// ---------------------------------------------------------------------------
__global__ void __launch_bounds__(256) transpose_kernel(
    const float* __restrict__ qk, const float* __restrict__ val,
    const unsigned int* __restrict__ idx_raw,
    float* __restrict__ cent)
{
    __shared__ float tile[D][NTILE + 1];
    __shared__ unsigned int s_any;

    const int blk   = blockIdx.x;
    const int ntile = blk % NBLK_N;
    const int bg    = blk / NBLK_N;
    const int g     = bg % G;
    const int b     = bg / G;
    const int n0    = ntile * NTILE;
    const int tid   = threadIdx.x;

    // ---- block 0: idx dtype detection (cheap, overlapped with transpose) ----
    if (blk == 0) {
        if (tid == 0) s_any = 0u;
        __syncthreads();
        unsigned int v = idx_raw[2 * tid + 1] |
                         idx_raw[2 * (tid + 256) + 1] |
                         idx_raw[2 * (tid + 512) + 1] |
                         idx_raw[2 * (tid + 768) + 1];
        if (v) atomicOr(&s_any, 1u);
        __syncthreads();
        if (tid == 0) g_idx_is64 = (s_any == 0u) ? 1 : 0;
    }

    // ---- zero this block's 64-element slice of centrality ----
    if (cent != nullptr && tid < 64)
        cent[(size_t)blk * 64 + tid] = 0.0f;

    const size_t src_off = ((size_t)b * C + (size_t)g * D) * N + n0;
    const size_t dst_off = ((size_t)bg * N + n0) * D;

    {
        const float* src = qk + src_off;
        float* dst = g_qk_t + dst_off;
        #pragma unroll
        for (int r = 0; r < 4; r++) {
            int e = tid + r * 256;
            int j = e >> 6, nn = e & 63;
            tile[j][nn] = src[(size_t)j * N + nn];
        }
        __syncthreads();
        #pragma unroll
        for (int r = 0; r < 4; r++) {
            int e = tid + r * 256;
            int nn = e >> 4, j = e & 15;
            dst[nn * D + j] = tile[j][nn];
        }
        __syncthreads();
    }
    {
        const float* src = val + src_off;
        float* dst = g_v_t + dst_off;
        #pragma unroll
        for (int r = 0; r < 4; r++) {
            int e = tid + r * 256;
            int j = e >> 6, nn = e & 63;
            tile[j][nn] = src[(size_t)j * N + nn];
        }
        __syncthreads();
        #pragma unroll
        for (int r = 0; r < 4; r++) {
            int e = tid + r * 256;
            int nn = e >> 4, j = e & 15;
            dst[nn * D + j] = tile[j][nn];
        }
    }
}

// ---------------------------------------------------------------------------
// Main fused kernel: attention + softmax + feature + centrality scatter.
// 4 lanes per point (float4 over the 16 channels), 64 points per 256-thr block.
// ---------------------------------------------------------------------------
__global__ void __launch_bounds__(256) attn_kernel(
    const void* __restrict__ idx_raw,
    float* __restrict__ out,           // feature region
    float* __restrict__ cent)          // centrality region (may be null)
{
    const float4* __restrict__ qkt = reinterpret_cast<const float4*>(g_qk_t);
    const float4* __restrict__ vt  = reinterpret_cast<const float4*>(g_v_t);

    const int blk   = blockIdx.x;
    const int ntile = blk % NBLK_N;
    const int bg    = blk / NBLK_N;
    const int g     = bg % G;
    const int b     = bg / G;
    const int n0    = ntile * NTILE;

    const int tid  = threadIdx.x;
    const int p    = tid >> 2;          // point within tile (0..63)
    const int L    = tid & 3;           // lane within point (4 channels each)
    const int n    = n0 + p;
    const int lane = tid & 31;
    const int base_lane = lane & ~3;
    const unsigned FULL = 0xffffffffu;

    const size_t bgN = (size_t)bg * N;

    // --- load this lane's 4 neighbor indices (dtype-dispatched), clamp ---
    const size_t ibase = ((size_t)b * N + n) * K + 4 * L;
    int my_idx[4];
    if (g_idx_is64) {
        const long long* ip = reinterpret_cast<const long long*>(idx_raw) + ibase;
        longlong2 e0 = *reinterpret_cast<const longlong2*>(ip);
        longlong2 e1 = *reinterpret_cast<const longlong2*>(ip + 2);
        my_idx[0] = (int)e0.x; my_idx[1] = (int)e0.y;
        my_idx[2] = (int)e1.x; my_idx[3] = (int)e1.y;
    } else {
        int4 e = *reinterpret_cast<const int4*>(
            reinterpret_cast<const int*>(idx_raw) + ibase);
        my_idx[0] = e.x; my_idx[1] = e.y; my_idx[2] = e.z; my_idx[3] = e.w;
    }
    #pragma unroll
    for (int i = 0; i < 4; i++)
        my_idx[i] = min(max(my_idx[i], 0), N - 1);   // structural OOB guard

    // broadcast all 16 indices to each lane of the 4-lane group
    int ms[16];
    #pragma unroll
    for (int k = 0; k < 16; k++)
        ms[k] = __shfl_sync(FULL, my_idx[k & 3], base_lane + (k >> 2));

    // --- query vector (this lane's 4 channels) ---
    const float4 q = qkt[(bgN + n) * 4 + L];

    // --- attention logits: dot(q, key[m_k]) reduced over 4 lanes ---
    float att[16];
    #pragma unroll
    for (int k = 0; k < 16; k++) {
        float4 kk = qkt[(bgN + (size_t)ms[k]) * 4 + L];
        float s = fmaf(q.x, kk.x, fmaf(q.y, kk.y, fmaf(q.z, kk.z, q.w * kk.w)));
        s += __shfl_xor_sync(FULL, s, 1);
        s += __shfl_xor_sync(FULL, s, 2);
        att[k] = s;                     // all 4 lanes hold identical value
    }

    // --- softmax over K=16 (redundant per lane, registers only) ---
    float mx = att[0];
    #pragma unroll
    for (int k = 1; k < 16; k++) mx = fmaxf(mx, att[k]);
    float sum = 0.0f;
    #pragma unroll
    for (int k = 0; k < 16; k++) { att[k] = __expf(att[k] - mx); sum += att[k]; }
    const float inv = 1.0f / sum;
    #pragma unroll
    for (int k = 0; k < 16; k++) att[k] *= inv;

    // --- feature: sum_k att[k] * value[m_k] (this lane's 4 channels) ---
    float4 acc = make_float4(0.f, 0.f, 0.f, 0.f);
    #pragma unroll
    for (int k = 0; k < 16; k++) {
        float4 vv = vt[(bgN + (size_t)ms[k]) * 4 + L];
        acc.x = fmaf(att[k], vv.x, acc.x);
        acc.y = fmaf(att[k], vv.y, acc.y);
        acc.z = fmaf(att[k], vv.z, acc.z);
        acc.w = fmaf(att[k], vv.w, acc.w);
    }

    // --- centrality scatter: each lane handles its own 4 neighbors ---
    if (cent != nullptr) {
        #pragma unroll
        for (int i = 0; i < 4; i++)
            atomicAdd(&cent[bgN + (size_t)my_idx[i]], att[4 * L + i]);
    }

    // --- stage feature in smem, write coalesced in (B, C, N) layout ---
    __shared__ float ftile[NTILE][D + 1];
    ftile[p][4 * L + 0] = acc.x;
    ftile[p][4 * L + 1] = acc.y;
    ftile[p][4 * L + 2] = acc.z;
    ftile[p][4 * L + 3] = acc.w;
    __syncthreads();

    float* fout = out + ((size_t)b * C + (size_t)g * D) * N + n0;
    #pragma unroll
    for (int r = 0; r < 4; r++) {
        int e = tid + r * 256;
        int j = e >> 6, nn = e & 63;
        fout[(size_t)j * N + nn] = ftile[nn][j];
    }
}

// ---------------------------------------------------------------------------
// Launch
// ---------------------------------------------------------------------------
extern "C" void kernel_launch(void* const* d_in, const int* in_sizes, int n_in,
                              void* d_out, int out_size)
{
    // Resolve inputs by element count (robust to ordering):
    //   queryandkey / value: the two inputs with B*C*N elements (qk first)
    //   idx_knn: the input with B*N*K elements
    const float* qk  = nullptr;
    const float* val = nullptr;
    const void*  idx = nullptr;

    for (int i = 0; i < n_in; i++) {
        if (in_sizes[i] == FEAT_ELEMS) {
            if (qk == nullptr)       qk  = (const float*)d_in[i];
            else if (val == nullptr) val = (const float*)d_in[i];
        } else if (in_sizes[i] == IDX_ELEMS) {
            idx = d_in[i];
        }
    }
    if (qk == nullptr || val == nullptr || idx == nullptr) {
        qk  = (const float*)d_in[4];
        val = (const float*)d_in[5];
        idx = d_in[6];
    }

    float* out  = (float*)d_out;                   // feature (B*C*N) first
    float* cent = nullptr;                         // then centrality (B*G*N)
    if (out_size >= FEAT_ELEMS + CENT_ELEMS)
        cent = out + (size_t)FEAT_ELEMS;

    transpose_kernel<<<NBLOCKS, 256>>>(qk, val, (const unsigned int*)idx, cent);
    attn_kernel<<<NBLOCKS, 256>>>(idx, out, cent);
}